// round 12
// baseline (speedup 1.0000x reference)
#include <cuda_runtime.h>
#include <cstdint>

// ============================================================================
// SpecAttn via mma.sync tf32 (HMMA). R12 = R8 structure (cvt pass, MODE1
// partials + rowsum_reduce, 128x128/BK32/ST2/128thr/2CTA GEMM) +
//  - transpose4: all 4 weight transposes in one launch
//  - mainloop fragment loads as asm LDS.64 with IMMEDIATE offsets from two
//    per-stage base registers (kills the 29% ALU pipe load seen in ncu)
// ============================================================================

#define BM 128
#define BN 128
#define BK 32
#define ST 2
#define ROWF 40                        // 32 + 8 pad; ROWF%32==8 -> LDS.64 conflict-free
#define TILE_F (BM * ROWF)             // 5120 floats
#define STAGE_F (2 * TILE_F)
#define SMEM_BYTES (ST * STAGE_F * 4)  // 81920 B

#define MSROWS 16384                   // B*S

// ---------------- scratch (device globals; no allocations) ------------------
__device__ float g_xc  [8L*2048*1024];
__device__ float g_qk  [16384L*2048];   // [B*S, 2048]: cols 0-1023 = Q, 1024+ = K
__device__ float g_vt  [8L*1024*2048];  // per batch [H, S]
__device__ float g_ctx [8L*2048*1024];
__device__ float g_e   [8L*2048*2048];
__device__ float g_wqkT[2048L*1024];    // rows 0-1023 wq^T, 1024+ wk^T
__device__ float g_wvT [1024L*1024];
__device__ float g_woT [1024L*1024];
__device__ float g_bqk [2048];
__device__ float g_rsp [32L*MSROWS];    // per-(bx,nwarp) row-sum partials
__device__ float g_rs  [MSROWS];        // reduced row sums

// ---------------- helpers ----------------------------------------------------
__device__ __forceinline__ uint32_t smem_u32(const void* p) {
    uint32_t a;
    asm("{ .reg .u64 t; cvta.to.shared.u64 t, %1; cvt.u32.u64 %0, t; }" : "=r"(a) : "l"(p));
    return a;
}
__device__ __forceinline__ float to_tf32(float x) {
    uint32_t u;
    asm("cvt.rna.tf32.f32 %0, %1;" : "=r"(u) : "f"(x));
    return __uint_as_float(u);
}
__device__ __forceinline__ void mma_tf32(float* c, const uint32_t* a, const uint32_t* b) {
    asm volatile(
        "mma.sync.aligned.m16n8k8.row.col.f32.tf32.tf32.f32 "
        "{%0,%1,%2,%3},{%4,%5,%6,%7},{%8,%9},{%0,%1,%2,%3};"
        : "+f"(c[0]), "+f"(c[1]), "+f"(c[2]), "+f"(c[3])
        : "r"(a[0]), "r"(a[1]), "r"(a[2]), "r"(a[3]), "r"(b[0]), "r"(b[1]));
}

// LDS.64 with compile-time immediate offset: guarantees [R+imm] addressing.
template <int OFF>
__device__ __forceinline__ float2 lds64(uint32_t base) {
    float2 v;
    asm volatile("ld.shared.v2.f32 {%0,%1}, [%2+%3];"
                 : "=f"(v.x), "=f"(v.y) : "r"(base), "n"(OFF));
    return v;
}

template <int MT, int K8>
__device__ __forceinline__ void load_a(uint32_t aB, uint32_t (&a)[4]) {
    const float2 v0 = lds64<(MT * 16 * ROWF + K8) * 4>(aB);
    const float2 v1 = lds64<((MT * 16 + 8) * ROWF + K8) * 4>(aB);
    a[0] = __float_as_uint(v0.x); a[2] = __float_as_uint(v0.y);
    a[1] = __float_as_uint(v1.x); a[3] = __float_as_uint(v1.y);
}
template <int NT, int K8>
__device__ __forceinline__ void load_b(uint32_t bB, uint32_t (&b)[2]) {
    const float2 w = lds64<(NT * 8 * ROWF + K8) * 4>(bB);
    b[0] = __float_as_uint(w.x); b[1] = __float_as_uint(w.y);
}

// ============================================================================
// tf32 GEMM: C[z] = f( alpha * A[z] @ B[z]^T + bias )
//   BIAS: 0 none, 1 per-column, 2 per-row.
//   MODE: 0 plain, 1 f=exp + row-sum partials, 2 scale rows by 1/rowsum.
//   A: [M,K] rm (ld ldA).  B: [N,K] rm (ld ldB).  C: ld ldC.
// grid = (N/BN, M/BM, Z), block = 128 (4 warps, 2x2 grid, 64x64 warp tiles).
// k-slot relabel: MMA k-slot tg <- smem col k8+2tg, slot tg+4 <- k8+2tg+1.
// ============================================================================
template <int BIAS, bool CVT_OUT, int MODE>
__global__ __launch_bounds__(128, 2)
void tf32_gemm(const float* __restrict__ A, const float* __restrict__ Bm,
               const float* __restrict__ bias, float* __restrict__ C,
               int K, int ldA, int ldB, int ldC,
               long sA, long sB, long sC, float alpha,
               const float* __restrict__ rsum, float* __restrict__ rsp,
               long rsStride)
{
    extern __shared__ float smf[];
    const uint32_t sbase = smem_u32(smf);
    const int tid = threadIdx.x;

    A  += (long)blockIdx.z * sA;
    Bm += (long)blockIdx.z * sB;
    C  += (long)blockIdx.z * sC;
    const long rowBase = (long)blockIdx.y * BM;
    const long colBase = (long)blockIdx.x * BN;
    const long rsBase  = (long)blockIdx.z * rsStride + rowBase;

    // ---- global->smem mapping: thread covers rows (tid>>3)+16i, seg tid&7 ----
    const int lr = tid >> 3;           // 0..15
    const int ls = tid & 7;            // 16B segment within 128B row
    const uint32_t off0 = (uint32_t)(lr * ROWF + ls * 4) * 4;
    const float* Ag = A  + (rowBase + lr) * (long)ldA + ls * 4;
    const float* Bg = Bm + (colBase + lr) * (long)ldB + ls * 4;

    const int NT = K >> 5;

#define LOAD_STAGE(sbuf, kt) do {                                              \
    const uint32_t st_ = sbase + (uint32_t)(sbuf) * (STAGE_F * 4);             \
    const uint32_t bt_ = st_ + TILE_F * 4;                                     \
    const long ko_ = (long)(kt) * BK;                                          \
    _Pragma("unroll")                                                          \
    for (int i_ = 0; i_ < 8; i_++) {                                           \
        asm volatile("cp.async.cg.shared.global [%0],[%1],16;"                 \
            :: "r"(st_ + off0 + (uint32_t)i_ * (16 * ROWF * 4)),               \
               "l"(Ag + ko_ + (long)16 * i_ * ldA) : "memory");                \
        asm volatile("cp.async.cg.shared.global [%0],[%1],16;"                 \
            :: "r"(bt_ + off0 + (uint32_t)i_ * (16 * ROWF * 4)),               \
               "l"(Bg + ko_ + (long)16 * i_ * ldB) : "memory");                \
    }                                                                          \
    asm volatile("cp.async.commit_group;" ::: "memory");                       \
} while (0)

    // prologue
    LOAD_STAGE(0, 0);

    // ---- warp tiling: 2x2 warp grid, 64x64 per warp ----
    const int warp = tid >> 5, lane = tid & 31;
    const int grp = lane >> 2, tg = lane & 3;
    const int mbase = (warp & 1) * 64;
    const int nbase = (warp >> 1) * 64;

    // per-thread smem base offsets (bytes) for fragment loads
    const uint32_t aOff = (uint32_t)(((mbase + grp) * ROWF + 2 * tg) * 4);
    const uint32_t bOff = (uint32_t)(TILE_F * 4) +
                          (uint32_t)(((nbase + grp) * ROWF + 2 * tg) * 4);

    float acc[4][8][4];
    #pragma unroll
    for (int mt = 0; mt < 4; mt++)
        #pragma unroll
        for (int nt = 0; nt < 8; nt++)
            #pragma unroll
            for (int j = 0; j < 4; j++) acc[mt][nt][j] = 0.f;

#define DO_K8(K8, aB, bB) do {                                                 \
    uint32_t a[4][4], b[8][2];                                                 \
    load_a<0, K8>(aB, a[0]); load_a<1, K8>(aB, a[1]);                          \
    load_a<2, K8>(aB, a[2]); load_a<3, K8>(aB, a[3]);                          \
    load_b<0, K8>(bB, b[0]); load_b<1, K8>(bB, b[1]);                          \
    load_b<2, K8>(bB, b[2]); load_b<3, K8>(bB, b[3]);                          \
    load_b<4, K8>(bB, b[4]); load_b<5, K8>(bB, b[5]);                          \
    load_b<6, K8>(bB, b[6]); load_b<7, K8>(bB, b[7]);                          \
    _Pragma("unroll")                                                          \
    for (int mt = 0; mt < 4; mt++)                                             \
        _Pragma("unroll")                                                      \
        for (int nt = 0; nt < 8; nt++)                                         \
            mma_tf32(acc[mt][nt], a[mt], b[nt]);                               \
} while (0)

    for (int t = 0; t < NT; ++t) {
        asm volatile("cp.async.wait_group 0;" ::: "memory");
        __syncthreads();
        if (t + 1 < NT) LOAD_STAGE((t + 1) & 1, t + 1);

        const uint32_t stageB = sbase + (uint32_t)(t & 1) * (STAGE_F * 4);
        const uint32_t aB = stageB + aOff;
        const uint32_t bB = stageB + bOff;

        DO_K8(0,  aB, bB);
        DO_K8(8,  aB, bB);
        DO_K8(16, aB, bB);
        DO_K8(24, aB, bB);
    }

    // ---- epilogue (mt-outer so MODE 1/2 and row-bias work per-row) ----
    float2 bv[8];
    #pragma unroll
    for (int nt = 0; nt < 8; nt++) {
        if (BIAS == 1) bv[nt] = *(const float2*)(bias + colBase + nbase + nt * 8 + tg * 2);
        else           bv[nt] = make_float2(0.f, 0.f);
    }

    #pragma unroll
    for (int mt = 0; mt < 4; mt++) {
        const int rloc = mbase + mt * 16 + grp;      // local row (and +8)
        const long r0 = rowBase + rloc;
        float rb0 = 0.f, rb1 = 0.f;
        if (BIAS == 2) {
            rb0 = bias[r0];
            rb1 = bias[r0 + 8];
        }
        float inv0 = 1.f, inv1 = 1.f;
        if (MODE == 2) {
            inv0 = 1.f / rsum[rsBase + rloc];
            inv1 = 1.f / rsum[rsBase + rloc + 8];
        }
        float rs0 = 0.f, rs1 = 0.f;
        #pragma unroll
        for (int nt = 0; nt < 8; nt++) {
            const long col = colBase + nbase + nt * 8 + tg * 2;
            float o0 = acc[mt][nt][0] * alpha + bv[nt].x + rb0;
            float o1 = acc[mt][nt][1] * alpha + bv[nt].y + rb0;
            float o2 = acc[mt][nt][2] * alpha + bv[nt].x + rb1;
            float o3 = acc[mt][nt][3] * alpha + bv[nt].y + rb1;
            if (MODE == 1) {
                o0 = __expf(o0); o1 = __expf(o1);
                o2 = __expf(o2); o3 = __expf(o3);
                rs0 += o0 + o1;  rs1 += o2 + o3;
            }
            if (MODE == 2) {
                o0 *= inv0; o1 *= inv0; o2 *= inv1; o3 *= inv1;
            }
            if (CVT_OUT) {
                o0 = to_tf32(o0); o1 = to_tf32(o1);
                o2 = to_tf32(o2); o3 = to_tf32(o3);
            }
            *(float2*)(C + r0 * (long)ldC + col)       = make_float2(o0, o1);
            *(float2*)(C + (r0 + 8) * (long)ldC + col) = make_float2(o2, o3);
        }
        if (MODE == 1) {
            rs0 += __shfl_xor_sync(~0u, rs0, 1);
            rs0 += __shfl_xor_sync(~0u, rs0, 2);
            rs1 += __shfl_xor_sync(~0u, rs1, 1);
            rs1 += __shfl_xor_sync(~0u, rs1, 2);
            if (tg == 0) {
                const long slot = ((long)blockIdx.x * 2 + (warp >> 1)) * MSROWS + rsBase + rloc;
                rsp[slot]     = rs0;
                rsp[slot + 8] = rs1;
            }
        }
    }
#undef LOAD_STAGE
#undef DO_K8
}

// ============================================================================
// reduce 32 row-sum partials per row -> rowsum.
// ============================================================================
__global__ __launch_bounds__(256)
void rowsum_reduce(const float* __restrict__ rsp, float* __restrict__ rsum)
{
    const int i = blockIdx.x * 256 + threadIdx.x;
    float s = 0.f;
    #pragma unroll
    for (int j = 0; j < 32; j++) s += rsp[(long)j * MSROWS + i];
    rsum[i] = s;
}

// ============================================================================
// batched 1024x1024 transpose + tf32 round: 4 weights in one launch (z=0..3).
// ============================================================================
__global__ __launch_bounds__(256)
void transpose4_kernel(const float* __restrict__ s0, const float* __restrict__ s1,
                       const float* __restrict__ s2, const float* __restrict__ s3,
                       float* __restrict__ d0, float* __restrict__ d1,
                       float* __restrict__ d2, float* __restrict__ d3)
{
    __shared__ float tile[32][33];
    const float* src = (blockIdx.z == 0) ? s0 : (blockIdx.z == 1) ? s1
                     : (blockIdx.z == 2) ? s2 : s3;
    float* dst = (blockIdx.z == 0) ? d0 : (blockIdx.z == 1) ? d1
               : (blockIdx.z == 2) ? d2 : d3;
    const int c0 = blockIdx.x * 32, r0 = blockIdx.y * 32;
    const int tx = threadIdx.x, ty = threadIdx.y;
    #pragma unroll
    for (int i = ty; i < 32; i += 8)
        tile[i][tx] = to_tf32(src[(long)(r0 + i) * 1024 + c0 + tx]);
    __syncthreads();
    #pragma unroll
    for (int i = ty; i < 32; i += 8)
        dst[(long)(c0 + i) * 1024 + r0 + tx] = tile[tx][i];
}

// elementwise tf32 round (for x)
__global__ __launch_bounds__(256)
void cvt_kernel(const float4* __restrict__ in, float4* __restrict__ out, long n4)
{
    long i = blockIdx.x * 256L + threadIdx.x;
    const long stride = gridDim.x * 256L;
    for (; i < n4; i += stride) {
        float4 v = in[i];
        v.x = to_tf32(v.x); v.y = to_tf32(v.y);
        v.z = to_tf32(v.z); v.w = to_tf32(v.w);
        out[i] = v;
    }
}

// ============================================================================
extern "C" void kernel_launch(void* const* d_in, const int* in_sizes, int n_in,
                              void* d_out, int out_size)
{
    (void)in_sizes; (void)n_in; (void)out_size;
    const float* x  = (const float*)d_in[0];
    const float* wq = (const float*)d_in[1];
    const float* bq = (const float*)d_in[2];
    const float* wk = (const float*)d_in[3];
    const float* bk = (const float*)d_in[4];
    const float* wv = (const float*)d_in[5];
    const float* bv = (const float*)d_in[6];
    const float* wo = (const float*)d_in[7];
    const float* bo = (const float*)d_in[8];
    float* out = (float*)d_out;

    float *xc, *qk, *vt, *ctx, *e, *wqkT, *wvT, *woT, *bqk, *rsp, *rs;
    cudaGetSymbolAddress((void**)&xc,   g_xc);
    cudaGetSymbolAddress((void**)&qk,   g_qk);
    cudaGetSymbolAddress((void**)&vt,   g_vt);
    cudaGetSymbolAddress((void**)&ctx,  g_ctx);
    cudaGetSymbolAddress((void**)&e,    g_e);
    cudaGetSymbolAddress((void**)&wqkT, g_wqkT);
    cudaGetSymbolAddress((void**)&wvT,  g_wvT);
    cudaGetSymbolAddress((void**)&woT,  g_woT);
    cudaGetSymbolAddress((void**)&bqk,  g_bqk);
    cudaGetSymbolAddress((void**)&rsp,  g_rsp);
    cudaGetSymbolAddress((void**)&rs,   g_rs);

    cudaFuncSetAttribute(tf32_gemm<1, true,  0>, cudaFuncAttributeMaxDynamicSharedMemorySize, SMEM_BYTES);
    cudaFuncSetAttribute(tf32_gemm<2, true,  0>, cudaFuncAttributeMaxDynamicSharedMemorySize, SMEM_BYTES);
    cudaFuncSetAttribute(tf32_gemm<1, false, 0>, cudaFuncAttributeMaxDynamicSharedMemorySize, SMEM_BYTES);
    cudaFuncSetAttribute(tf32_gemm<0, true,  1>, cudaFuncAttributeMaxDynamicSharedMemorySize, SMEM_BYTES);
    cudaFuncSetAttribute(tf32_gemm<0, true,  2>, cudaFuncAttributeMaxDynamicSharedMemorySize, SMEM_BYTES);

    const int Bsz = 8, S = 2048, H = 1024;
    const int MS = Bsz * S;                 // 16384
    const float scale = 0.03125f;           // 1/sqrt(1024)

    // pre-round x to tf32
    cvt_kernel<<<1024, 256>>>((const float4*)x, (float4*)xc, (long)MS * H / 4);

    // all 4 weight transposes in one launch (wqkT: rows 0-1023 wq^T, 1024+ wk^T)
    transpose4_kernel<<<dim3(32, 32, 4), dim3(32, 8)>>>(
        wq, wk, wv, wo, wqkT, wqkT + (long)H * H, wvT, woT);
    cudaMemcpyAsync(bqk,     bq, H * sizeof(float), cudaMemcpyDeviceToDevice);
    cudaMemcpyAsync(bqk + H, bk, H * sizeof(float), cudaMemcpyDeviceToDevice);

    dim3 blk(128);

    // Q+K projection, merged: qk[MS, 2048] = xc @ wqkT^T + bqk
    tf32_gemm<1, true, 0><<<dim3(2 * H / BN, MS / BM, 1), blk, SMEM_BYTES>>>(
        xc, wqkT, bqk, qk, H, H, H, 2 * H, 0, 0, 0, 1.f, nullptr, nullptr, 0);

    // V, produced transposed: vt[b] (H x S) = wvT @ x[b]^T + bv (row bias)
    tf32_gemm<2, true, 0><<<dim3(S / BN, H / BM, Bsz), blk, SMEM_BYTES>>>(
        wvT, xc, bv, vt, H, H, H, S,
        0, (long)S * H, (long)H * S, 1.f, nullptr, nullptr, 0);

    // Energy + exp fused: P = exp(scale * Q @ K^T), row-sum partials emitted.
    tf32_gemm<0, true, 1><<<dim3(S / BN, S / BM, Bsz), blk, SMEM_BYTES>>>(
        qk, qk + H, nullptr, e, H, 2 * H, 2 * H, S,
        (long)S * 2 * H, (long)S * 2 * H, (long)S * S, scale,
        nullptr, rsp, (long)S);

    rowsum_reduce<<<MS / 256, 256>>>(rsp, rs);

    // Context: ctx = (P @ V) / rowsum
    tf32_gemm<0, true, 2><<<dim3(H / BN, S / BM, Bsz), blk, SMEM_BYTES>>>(
        e, vt, nullptr, ctx, S, S, S, H,
        (long)S * S, (long)H * S, (long)S * H, 1.f, rs, nullptr, (long)S);

    // Output projection
    tf32_gemm<1, false, 0><<<dim3(H / BN, MS / BM, 1), blk, SMEM_BYTES>>>(
        ctx, woT, bo, out, H, H, H, H, 0, 0, 0, 1.f, nullptr, nullptr, 0);
}

// round 13
// speedup vs baseline: 1.5240x; 1.5240x over previous
#include <cuda_runtime.h>
#include <cstdint>

// ============================================================================
// SpecAttn via mma.sync tf32 (HMMA). R13 = R10 kernel EXACTLY (cvt pass,
// MODE1 partials + rowsum_reduce, 128x128/BK32/ST2/128thr/2CTA, C++ float2
// fragment loads, compiler-scheduled) with two safe deltas:
//  - LDA/LDB/LDC/K as TEMPLATE constants -> cp.async addresses become
//    [R+imm] (kills mainloop 64-bit IMAD chains, the 17-29% ALU pipe load)
//  - transpose4: all 4 weight transposes in one launch
// ============================================================================

#define BM 128
#define BN 128
#define BK 32
#define ST 2
#define ROWF 40                        // 32 + 8 pad; ROWF%32==8 -> LDS.64 conflict-free
#define TILE_F (BM * ROWF)             // 5120 floats
#define STAGE_F (2 * TILE_F)
#define SMEM_BYTES (ST * STAGE_F * 4)  // 81920 B

#define MSROWS 16384                   // B*S

// ---------------- scratch (device globals; no allocations) ------------------
__device__ float g_xc  [8L*2048*1024];
__device__ float g_qk  [16384L*2048];   // [B*S, 2048]: cols 0-1023 = Q, 1024+ = K
__device__ float g_vt  [8L*1024*2048];  // per batch [H, S]
__device__ float g_ctx [8L*2048*1024];
__device__ float g_e   [8L*2048*2048];
__device__ float g_wqkT[2048L*1024];    // rows 0-1023 wq^T, 1024+ wk^T
__device__ float g_wvT [1024L*1024];
__device__ float g_woT [1024L*1024];
__device__ float g_bqk [2048];
__device__ float g_rsp [32L*MSROWS];    // per-(bx,nwarp) row-sum partials
__device__ float g_rs  [MSROWS];        // reduced row sums

// ---------------- helpers ----------------------------------------------------
__device__ __forceinline__ uint32_t smem_u32(const void* p) {
    uint32_t a;
    asm("{ .reg .u64 t; cvta.to.shared.u64 t, %1; cvt.u32.u64 %0, t; }" : "=r"(a) : "l"(p));
    return a;
}
__device__ __forceinline__ float to_tf32(float x) {
    uint32_t u;
    asm("cvt.rna.tf32.f32 %0, %1;" : "=r"(u) : "f"(x));
    return __uint_as_float(u);
}
__device__ __forceinline__ void mma_tf32(float* c, const uint32_t* a, const uint32_t* b) {
    asm volatile(
        "mma.sync.aligned.m16n8k8.row.col.f32.tf32.tf32.f32 "
        "{%0,%1,%2,%3},{%4,%5,%6,%7},{%8,%9},{%0,%1,%2,%3};"
        : "+f"(c[0]), "+f"(c[1]), "+f"(c[2]), "+f"(c[3])
        : "r"(a[0]), "r"(a[1]), "r"(a[2]), "r"(a[3]), "r"(b[0]), "r"(b[1]));
}
__device__ __forceinline__ uint32_t fbits(float x) { return __float_as_uint(x); }

// ============================================================================
// tf32 GEMM: C[z] = f( alpha * A[z] @ B[z]^T + bias )
//   BIAS: 0 none, 1 per-column, 2 per-row.
//   MODE: 0 plain, 1 f=exp + row-sum partials, 2 scale rows by 1/rowsum.
//   LDA/LDB/LDC/K: compile-time leading dims / depth -> [R+imm] addressing.
// grid = (N/BN, M/BM, Z), block = 128 (4 warps, 2x2 grid, 64x64 warp tiles).
// k-slot relabel: MMA k-slot tg <- smem col k8+2tg, slot tg+4 <- k8+2tg+1.
// ============================================================================
template <int BIAS, bool CVT_OUT, int MODE, int LDA, int LDB, int LDC, int K>
__global__ __launch_bounds__(128, 2)
void tf32_gemm(const float* __restrict__ A, const float* __restrict__ Bm,
               const float* __restrict__ bias, float* __restrict__ C,
               long sA, long sB, long sC, float alpha,
               const float* __restrict__ rsum, float* __restrict__ rsp,
               long rsStride)
{
    extern __shared__ float smf[];
    const uint32_t sbase = smem_u32(smf);
    const int tid = threadIdx.x;

    A  += (long)blockIdx.z * sA;
    Bm += (long)blockIdx.z * sB;
    C  += (long)blockIdx.z * sC;
    const long rowBase = (long)blockIdx.y * BM;
    const long colBase = (long)blockIdx.x * BN;
    const long rsBase  = (long)blockIdx.z * rsStride + rowBase;

    // ---- global->smem mapping: thread covers rows (tid>>3)+16i, seg tid&7 ----
    const int lr = tid >> 3;           // 0..15
    const int ls = tid & 7;            // 16B segment within 128B row
    const uint32_t off0 = (uint32_t)(lr * ROWF + ls * 4) * 4;
    const float* Ag = A  + (rowBase + lr) * (long)LDA + ls * 4;
    const float* Bg = Bm + (colBase + lr) * (long)LDB + ls * 4;

    const int NT = K >> 5;

#define LOAD_STAGE(sbuf, kt) do {                                              \
    const uint32_t st_ = sbase + (uint32_t)(sbuf) * (STAGE_F * 4);             \
    const uint32_t bt_ = st_ + TILE_F * 4;                                     \
    const int ko_ = (kt) * BK;                                                 \
    _Pragma("unroll")                                                          \
    for (int i_ = 0; i_ < 8; i_++) {                                           \
        asm volatile("cp.async.cg.shared.global [%0],[%1],16;"                 \
            :: "r"(st_ + off0 + (uint32_t)i_ * (16 * ROWF * 4)),               \
               "l"(Ag + ko_ + 16 * i_ * LDA) : "memory");                      \
        asm volatile("cp.async.cg.shared.global [%0],[%1],16;"                 \
            :: "r"(bt_ + off0 + (uint32_t)i_ * (16 * ROWF * 4)),               \
               "l"(Bg + ko_ + 16 * i_ * LDB) : "memory");                      \
    }                                                                          \
    asm volatile("cp.async.commit_group;" ::: "memory");                       \
} while (0)

    // prologue
    LOAD_STAGE(0, 0);

    // ---- warp tiling: 2x2 warp grid, 64x64 per warp ----
    const int warp = tid >> 5, lane = tid & 31;
    const int grp = lane >> 2, tg = lane & 3;
    const int mbase = (warp & 1) * 64;
    const int nbase = (warp >> 1) * 64;

    float acc[4][8][4];
    #pragma unroll
    for (int mt = 0; mt < 4; mt++)
        #pragma unroll
        for (int nt = 0; nt < 8; nt++)
            #pragma unroll
            for (int j = 0; j < 4; j++) acc[mt][nt][j] = 0.f;

    for (int t = 0; t < NT; ++t) {
        asm volatile("cp.async.wait_group 0;" ::: "memory");
        __syncthreads();
        if (t + 1 < NT) LOAD_STAGE((t + 1) & 1, t + 1);

        const float* sAt = smf + (t & 1) * STAGE_F;
        const float* sBt = sAt + TILE_F;

        #pragma unroll
        for (int k8 = 0; k8 < BK; k8 += 8) {
            // k-slot relabel: MMA slot tg <- smem col k8+2tg, slot tg+4 <- k8+2tg+1
            uint32_t a[4][4], b[8][2];
            #pragma unroll
            for (int mt = 0; mt < 4; mt++) {
                const int r = mbase + mt * 16 + grp;
                const float2 v0 = *(const float2*)(sAt + r * ROWF + k8 + 2 * tg);
                const float2 v1 = *(const float2*)(sAt + (r + 8) * ROWF + k8 + 2 * tg);
                a[mt][0] = fbits(v0.x); a[mt][2] = fbits(v0.y);
                a[mt][1] = fbits(v1.x); a[mt][3] = fbits(v1.y);
            }
            #pragma unroll
            for (int nt = 0; nt < 8; nt++) {
                const float2 w = *(const float2*)(sBt + (nbase + nt * 8 + grp) * ROWF + k8 + 2 * tg);
                b[nt][0] = fbits(w.x); b[nt][1] = fbits(w.y);
            }
            #pragma unroll
            for (int mt = 0; mt < 4; mt++)
                #pragma unroll
                for (int nt = 0; nt < 8; nt++)
                    mma_tf32(acc[mt][nt], a[mt], b[nt]);
        }
    }

    // ---- epilogue (mt-outer so MODE 1/2 and row-bias work per-row) ----
    float2 bv[8];
    #pragma unroll
    for (int nt = 0; nt < 8; nt++) {
        if (BIAS == 1) bv[nt] = *(const float2*)(bias + colBase + nbase + nt * 8 + tg * 2);
        else           bv[nt] = make_float2(0.f, 0.f);
    }

    #pragma unroll
    for (int mt = 0; mt < 4; mt++) {
        const int rloc = mbase + mt * 16 + grp;      // local row (and +8)
        const long r0 = rowBase + rloc;
        float rb0 = 0.f, rb1 = 0.f;
        if (BIAS == 2) {
            rb0 = bias[r0];
            rb1 = bias[r0 + 8];
        }
        float inv0 = 1.f, inv1 = 1.f;
        if (MODE == 2) {
            inv0 = 1.f / rsum[rsBase + rloc];
            inv1 = 1.f / rsum[rsBase + rloc + 8];
        }
        float rs0 = 0.f, rs1 = 0.f;
        #pragma unroll
        for (int nt = 0; nt < 8; nt++) {
            const long col = colBase + nbase + nt * 8 + tg * 2;
            float o0 = acc[mt][nt][0] * alpha + bv[nt].x + rb0;
            float o1 = acc[mt][nt][1] * alpha + bv[nt].y + rb0;
            float o2 = acc[mt][nt][2] * alpha + bv[nt].x + rb1;
            float o3 = acc[mt][nt][3] * alpha + bv[nt].y + rb1;
            if (MODE == 1) {
                o0 = __expf(o0); o1 = __expf(o1);
                o2 = __expf(o2); o3 = __expf(o3);
                rs0 += o0 + o1;  rs1 += o2 + o3;
            }
            if (MODE == 2) {
                o0 *= inv0; o1 *= inv0; o2 *= inv1; o3 *= inv1;
            }
            if (CVT_OUT) {
                o0 = to_tf32(o0); o1 = to_tf32(o1);
                o2 = to_tf32(o2); o3 = to_tf32(o3);
            }
            *(float2*)(C + r0 * (long)LDC + col)       = make_float2(o0, o1);
            *(float2*)(C + (r0 + 8) * (long)LDC + col) = make_float2(o2, o3);
        }
        if (MODE == 1) {
            rs0 += __shfl_xor_sync(~0u, rs0, 1);
            rs0 += __shfl_xor_sync(~0u, rs0, 2);
            rs1 += __shfl_xor_sync(~0u, rs1, 1);
            rs1 += __shfl_xor_sync(~0u, rs1, 2);
            if (tg == 0) {
                const long slot = ((long)blockIdx.x * 2 + (warp >> 1)) * MSROWS + rsBase + rloc;
                rsp[slot]     = rs0;
                rsp[slot + 8] = rs1;
            }
        }
    }
#undef LOAD_STAGE
}

// ============================================================================
// reduce 32 row-sum partials per row -> rowsum.
// ============================================================================
__global__ __launch_bounds__(256)
void rowsum_reduce(const float* __restrict__ rsp, float* __restrict__ rsum)
{
    const int i = blockIdx.x * 256 + threadIdx.x;
    float s = 0.f;
    #pragma unroll
    for (int j = 0; j < 32; j++) s += rsp[(long)j * MSROWS + i];
    rsum[i] = s;
}

// ============================================================================
// batched 1024x1024 transpose + tf32 round: 4 weights in one launch (z=0..3).
// ============================================================================
__global__ __launch_bounds__(256)
void transpose4_kernel(const float* __restrict__ s0, const float* __restrict__ s1,
                       const float* __restrict__ s2, const float* __restrict__ s3,
                       float* __restrict__ d0, float* __restrict__ d1,
                       float* __restrict__ d2, float* __restrict__ d3)
{
    __shared__ float tile[32][33];
    const float* src = (blockIdx.z == 0) ? s0 : (blockIdx.z == 1) ? s1
                     : (blockIdx.z == 2) ? s2 : s3;
    float* dst = (blockIdx.z == 0) ? d0 : (blockIdx.z == 1) ? d1
               : (blockIdx.z == 2) ? d2 : d3;
    const int c0 = blockIdx.x * 32, r0 = blockIdx.y * 32;
    const int tx = threadIdx.x, ty = threadIdx.y;
    #pragma unroll
    for (int i = ty; i < 32; i += 8)
        tile[i][tx] = to_tf32(src[(long)(r0 + i) * 1024 + c0 + tx]);
    __syncthreads();
    #pragma unroll
    for (int i = ty; i < 32; i += 8)
        dst[(long)(c0 + i) * 1024 + r0 + tx] = tile[tx][i];
}

// elementwise tf32 round (for x)
__global__ __launch_bounds__(256)
void cvt_kernel(const float4* __restrict__ in, float4* __restrict__ out, long n4)
{
    long i = blockIdx.x * 256L + threadIdx.x;
    const long stride = gridDim.x * 256L;
    for (; i < n4; i += stride) {
        float4 v = in[i];
        v.x = to_tf32(v.x); v.y = to_tf32(v.y);
        v.z = to_tf32(v.z); v.w = to_tf32(v.w);
        out[i] = v;
    }
}

// ============================================================================
extern "C" void kernel_launch(void* const* d_in, const int* in_sizes, int n_in,
                              void* d_out, int out_size)
{
    (void)in_sizes; (void)n_in; (void)out_size;
    const float* x  = (const float*)d_in[0];
    const float* wq = (const float*)d_in[1];
    const float* bq = (const float*)d_in[2];
    const float* wk = (const float*)d_in[3];
    const float* bk = (const float*)d_in[4];
    const float* wv = (const float*)d_in[5];
    const float* bv = (const float*)d_in[6];
    const float* wo = (const float*)d_in[7];
    const float* bo = (const float*)d_in[8];
    float* out = (float*)d_out;

    float *xc, *qk, *vt, *ctx, *e, *wqkT, *wvT, *woT, *bqk, *rsp, *rs;
    cudaGetSymbolAddress((void**)&xc,   g_xc);
    cudaGetSymbolAddress((void**)&qk,   g_qk);
    cudaGetSymbolAddress((void**)&vt,   g_vt);
    cudaGetSymbolAddress((void**)&ctx,  g_ctx);
    cudaGetSymbolAddress((void**)&e,    g_e);
    cudaGetSymbolAddress((void**)&wqkT, g_wqkT);
    cudaGetSymbolAddress((void**)&wvT,  g_wvT);
    cudaGetSymbolAddress((void**)&woT,  g_woT);
    cudaGetSymbolAddress((void**)&bqk,  g_bqk);
    cudaGetSymbolAddress((void**)&rsp,  g_rsp);
    cudaGetSymbolAddress((void**)&rs,   g_rs);

    const int Bsz = 8, S = 2048, H = 1024;
    const int MS = Bsz * S;                 // 16384
    const float scale = 0.03125f;           // 1/sqrt(1024)

    // template instantiations: <BIAS, CVT_OUT, MODE, LDA, LDB, LDC, K>
    auto gemm_qkproj = tf32_gemm<1, true,  0, 1024, 1024, 2048, 1024>;
    auto gemm_vproj  = tf32_gemm<2, true,  0, 1024, 1024, 2048, 1024>;
    auto gemm_energy = tf32_gemm<0, true,  1, 2048, 2048, 2048, 1024>;
    auto gemm_ctx    = tf32_gemm<0, true,  2, 2048, 2048, 1024, 2048>;
    auto gemm_out    = tf32_gemm<1, false, 0, 1024, 1024, 1024, 1024>;

    cudaFuncSetAttribute(gemm_qkproj, cudaFuncAttributeMaxDynamicSharedMemorySize, SMEM_BYTES);
    cudaFuncSetAttribute(gemm_vproj,  cudaFuncAttributeMaxDynamicSharedMemorySize, SMEM_BYTES);
    cudaFuncSetAttribute(gemm_energy, cudaFuncAttributeMaxDynamicSharedMemorySize, SMEM_BYTES);
    cudaFuncSetAttribute(gemm_ctx,    cudaFuncAttributeMaxDynamicSharedMemorySize, SMEM_BYTES);
    cudaFuncSetAttribute(gemm_out,    cudaFuncAttributeMaxDynamicSharedMemorySize, SMEM_BYTES);

    // pre-round x to tf32
    cvt_kernel<<<1024, 256>>>((const float4*)x, (float4*)xc, (long)MS * H / 4);

    // all 4 weight transposes in one launch (wqkT: rows 0-1023 wq^T, 1024+ wk^T)
    transpose4_kernel<<<dim3(32, 32, 4), dim3(32, 8)>>>(
        wq, wk, wv, wo, wqkT, wqkT + (long)H * H, wvT, woT);
    cudaMemcpyAsync(bqk,     bq, H * sizeof(float), cudaMemcpyDeviceToDevice);
    cudaMemcpyAsync(bqk + H, bk, H * sizeof(float), cudaMemcpyDeviceToDevice);

    dim3 blk(128);

    // Q+K projection, merged: qk[MS, 2048] = xc @ wqkT^T + bqk
    gemm_qkproj<<<dim3(2 * H / BN, MS / BM, 1), blk, SMEM_BYTES>>>(
        xc, wqkT, bqk, qk, 0, 0, 0, 1.f, nullptr, nullptr, 0);

    // V, produced transposed: vt[b] (H x S) = wvT @ x[b]^T + bv (row bias)
    gemm_vproj<<<dim3(S / BN, H / BM, Bsz), blk, SMEM_BYTES>>>(
        wvT, xc, bv, vt, 0, (long)S * H, (long)H * S, 1.f, nullptr, nullptr, 0);

    // Energy + exp fused: P = exp(scale * Q @ K^T), row-sum partials emitted.
    gemm_energy<<<dim3(S / BN, S / BM, Bsz), blk, SMEM_BYTES>>>(
        qk, qk + H, nullptr, e,
        (long)S * 2 * H, (long)S * 2 * H, (long)S * S, scale,
        nullptr, rsp, (long)S);

    rowsum_reduce<<<MS / 256, 256>>>(rsp, rs);

    // Context: ctx = (P @ V) / rowsum
    gemm_ctx<<<dim3(H / BN, S / BM, Bsz), blk, SMEM_BYTES>>>(
        e, vt, nullptr, ctx,
        (long)S * S, (long)H * S, (long)S * H, 1.f, rs, nullptr, (long)S);

    // Output projection
    gemm_out<<<dim3(H / BN, MS / BM, 1), blk, SMEM_BYTES>>>(
        ctx, woT, bo, out, 0, 0, 0, 1.f, nullptr, nullptr, 0);
}

// round 14
// speedup vs baseline: 2.8062x; 1.8413x over previous
#include <cuda_runtime.h>
#include <cuda_fp16.h>
#include <cstdint>

// ============================================================================
// SpecAttn via mma.sync fp16 m16n8k16 (fp32 accumulate). R14: same validated
// skeleton (128x128 tile, 128 thr, 2x2 warp grid, 2 CTAs/SM, ST=2) but fp16
// operands: BK=64/iter, ONE LDS.64 per fragment (4tg k-relabel), half the
// HMMA count, half the smem/L2 traffic, half the barriers.
// Numerics: fp16 significand == tf32 significand (11 bits); energies bounded
// (|s|<~2.5) so P=exp(s) in [0.08, 12] — far from fp16 limits. fp32 accum.
// ============================================================================

#define BM 128
#define BN 128
#define BK 64                           // K halves per iteration
#define ST 2
#define ROWFH 80                        // 64 data + 16 pad halves; conflict-free
#define TILE_H (BM * ROWFH)             // 10240 halves = 20480 B
#define STAGE_H (2 * TILE_H)            // A + B per stage
#define SMEM_BYTES (ST * STAGE_H * 2)   // 81920 B -> 2 CTAs/SM

#define MSROWS 16384                    // B*S

// ---------------- scratch (device globals; no allocations) ------------------
__device__ __half g_xc  [8L*2048*1024];
__device__ __half g_qk  [16384L*2048];   // cols 0-1023 = Q, 1024+ = K
__device__ __half g_vt  [8L*1024*2048];  // per batch [H, S]
__device__ __half g_ctx [8L*2048*1024];
__device__ __half g_e   [8L*2048*2048];
__device__ __half g_wqkT[2048L*1024];    // rows 0-1023 wq^T, 1024+ wk^T
__device__ __half g_wvT [1024L*1024];
__device__ __half g_woT [1024L*1024];
__device__ float  g_bqk [2048];
__device__ float  g_rsp [32L*MSROWS];    // per-(bx,nwarp) row-sum partials
__device__ float  g_rs  [MSROWS];        // reduced row sums

// ---------------- helpers ----------------------------------------------------
__device__ __forceinline__ uint32_t smem_u32(const void* p) {
    uint32_t a;
    asm("{ .reg .u64 t; cvta.to.shared.u64 t, %1; cvt.u32.u64 %0, t; }" : "=r"(a) : "l"(p));
    return a;
}
__device__ __forceinline__ void mma_f16(float* c, const uint32_t* a, const uint32_t* b) {
    asm volatile(
        "mma.sync.aligned.m16n8k16.row.col.f32.f16.f16.f32 "
        "{%0,%1,%2,%3},{%4,%5,%6,%7},{%8,%9},{%0,%1,%2,%3};"
        : "+f"(c[0]), "+f"(c[1]), "+f"(c[2]), "+f"(c[3])
        : "r"(a[0]), "r"(a[1]), "r"(a[2]), "r"(a[3]), "r"(b[0]), "r"(b[1]));
}

// ============================================================================
// fp16 GEMM: C[z] = f( alpha * A[z] @ B[z]^T + bias )   (fp32 accumulate)
//   BIAS: 0 none, 1 per-column (fp32), 2 per-row (fp32).
//   MODE: 0 plain, 1 f=exp + row-sum partials, 2 scale rows by 1/rowsum.
//   HALF_OUT: store __half2 (intermediates) or float2 (final output).
//   LDA/LDB/LDC in halves (compile-time).  K mult of 64.
// grid = (N/BN, M/BM, Z), block = 128 (4 warps, 2x2 grid, 64x64 warp tiles).
// k16-group relabel: logical k slots {2tg,2tg+1,2tg+8,2tg+9} <- smem halves
// {4tg..4tg+3} of the group — one LDS.64 per fragment, bijective over tg,
// applied identically to A and B (contraction order within k16 is free).
// ============================================================================
template <int BIAS, int MODE, bool HALF_OUT, int LDA, int LDB, int LDC, int K>
__global__ __launch_bounds__(128, 2)
void h16_gemm(const __half* __restrict__ A, const __half* __restrict__ Bm,
              const float* __restrict__ bias, void* __restrict__ Cv,
              long sA, long sB, long sC, float alpha,
              const float* __restrict__ rsum, float* __restrict__ rsp,
              long rsStride)
{
    extern __shared__ __half smh[];
    const uint32_t sbase = smem_u32(smh);
    const int tid = threadIdx.x;

    A  += (long)blockIdx.z * sA;
    Bm += (long)blockIdx.z * sB;
    const long rowBase = (long)blockIdx.y * BM;
    const long colBase = (long)blockIdx.x * BN;
    const long rsBase  = (long)blockIdx.z * rsStride + rowBase;

    // ---- global->smem mapping: thread covers rows (tid>>3)+16i, seg tid&7 ----
    const int lr = tid >> 3;           // 0..15
    const int ls = tid & 7;            // 16B segment within 128B (64-half) row
    const uint32_t off0 = (uint32_t)(lr * (ROWFH * 2) + ls * 16);   // bytes
    const __half* Ag = A  + (rowBase + lr) * (long)LDA + ls * 8;
    const __half* Bg = Bm + (colBase + lr) * (long)LDB + ls * 8;

    const int NT = K / BK;

#define LOAD_STAGE(sbuf, kt) do {                                              \
    const uint32_t st_ = sbase + (uint32_t)(sbuf) * (STAGE_H * 2);             \
    const uint32_t bt_ = st_ + TILE_H * 2;                                     \
    const int ko_ = (kt) * BK;                                                 \
    _Pragma("unroll")                                                          \
    for (int i_ = 0; i_ < 8; i_++) {                                           \
        asm volatile("cp.async.cg.shared.global [%0],[%1],16;"                 \
            :: "r"(st_ + off0 + (uint32_t)i_ * (16 * ROWFH * 2)),              \
               "l"(Ag + ko_ + 16 * i_ * LDA) : "memory");                      \
        asm volatile("cp.async.cg.shared.global [%0],[%1],16;"                 \
            :: "r"(bt_ + off0 + (uint32_t)i_ * (16 * ROWFH * 2)),              \
               "l"(Bg + ko_ + 16 * i_ * LDB) : "memory");                      \
    }                                                                          \
    asm volatile("cp.async.commit_group;" ::: "memory");                       \
} while (0)

    // prologue
    LOAD_STAGE(0, 0);

    // ---- warp tiling: 2x2 warp grid, 64x64 per warp ----
    const int warp = tid >> 5, lane = tid & 31;
    const int grp = lane >> 2, tg = lane & 3;
    const int mbase = (warp & 1) * 64;
    const int nbase = (warp >> 1) * 64;

    float acc[4][8][4];
    #pragma unroll
    for (int mt = 0; mt < 4; mt++)
        #pragma unroll
        for (int nt = 0; nt < 8; nt++)
            #pragma unroll
            for (int j = 0; j < 4; j++) acc[mt][nt][j] = 0.f;

    for (int t = 0; t < NT; ++t) {
        asm volatile("cp.async.wait_group 0;" ::: "memory");
        __syncthreads();
        if (t + 1 < NT) LOAD_STAGE((t + 1) & 1, t + 1);

        const __half* sAt = smh + (t & 1) * STAGE_H;
        const __half* sBt = sAt + TILE_H;

        #pragma unroll
        for (int g = 0; g < 4; g++) {          // four k16 groups per BK=64
            const int gk = g * 16 + 4 * tg;    // halves offset of thread's 4
            uint32_t a[4][4], b[8][2];
            #pragma unroll
            for (int mt = 0; mt < 4; mt++) {
                const int r = mbase + mt * 16 + grp;
                const uint2 v0 = *(const uint2*)(sAt + r * ROWFH + gk);
                const uint2 v1 = *(const uint2*)(sAt + (r + 8) * ROWFH + gk);
                a[mt][0] = v0.x; a[mt][2] = v0.y;
                a[mt][1] = v1.x; a[mt][3] = v1.y;
            }
            #pragma unroll
            for (int nt = 0; nt < 8; nt++) {
                const uint2 w = *(const uint2*)(sBt + (nbase + nt * 8 + grp) * ROWFH + gk);
                b[nt][0] = w.x; b[nt][1] = w.y;
            }
            #pragma unroll
            for (int mt = 0; mt < 4; mt++)
                #pragma unroll
                for (int nt = 0; nt < 8; nt++)
                    mma_f16(acc[mt][nt], a[mt], b[nt]);
        }
    }

    // ---- epilogue (mt-outer so MODE 1/2 and row-bias work per-row) ----
    float2 bv[8];
    #pragma unroll
    for (int nt = 0; nt < 8; nt++) {
        if (BIAS == 1) bv[nt] = *(const float2*)(bias + colBase + nbase + nt * 8 + tg * 2);
        else           bv[nt] = make_float2(0.f, 0.f);
    }

    __half* Ch = (__half*)Cv + (long)blockIdx.z * sC;
    float*  Cf = (float*)Cv  + (long)blockIdx.z * sC;

    #pragma unroll
    for (int mt = 0; mt < 4; mt++) {
        const int rloc = mbase + mt * 16 + grp;      // local row (and +8)
        const long r0 = rowBase + rloc;
        float rb0 = 0.f, rb1 = 0.f;
        if (BIAS == 2) {
            rb0 = bias[r0];
            rb1 = bias[r0 + 8];
        }
        float inv0 = 1.f, inv1 = 1.f;
        if (MODE == 2) {
            inv0 = 1.f / rsum[rsBase + rloc];
            inv1 = 1.f / rsum[rsBase + rloc + 8];
        }
        float rs0 = 0.f, rs1 = 0.f;
        #pragma unroll
        for (int nt = 0; nt < 8; nt++) {
            const long col = colBase + nbase + nt * 8 + tg * 2;
            float o0 = acc[mt][nt][0] * alpha + bv[nt].x + rb0;
            float o1 = acc[mt][nt][1] * alpha + bv[nt].y + rb0;
            float o2 = acc[mt][nt][2] * alpha + bv[nt].x + rb1;
            float o3 = acc[mt][nt][3] * alpha + bv[nt].y + rb1;
            if (MODE == 1) {
                o0 = __expf(o0); o1 = __expf(o1);
                o2 = __expf(o2); o3 = __expf(o3);
                rs0 += o0 + o1;  rs1 += o2 + o3;
            }
            if (MODE == 2) {
                o0 *= inv0; o1 *= inv0; o2 *= inv1; o3 *= inv1;
            }
            if (HALF_OUT) {
                *(__half2*)(Ch + r0 * (long)LDC + col)       = __floats2half2_rn(o0, o1);
                *(__half2*)(Ch + (r0 + 8) * (long)LDC + col) = __floats2half2_rn(o2, o3);
            } else {
                *(float2*)(Cf + r0 * (long)LDC + col)       = make_float2(o0, o1);
                *(float2*)(Cf + (r0 + 8) * (long)LDC + col) = make_float2(o2, o3);
            }
        }
        if (MODE == 1) {
            rs0 += __shfl_xor_sync(~0u, rs0, 1);
            rs0 += __shfl_xor_sync(~0u, rs0, 2);
            rs1 += __shfl_xor_sync(~0u, rs1, 1);
            rs1 += __shfl_xor_sync(~0u, rs1, 2);
            if (tg == 0) {
                const long slot = ((long)blockIdx.x * 2 + (warp >> 1)) * MSROWS + rsBase + rloc;
                rsp[slot]     = rs0;
                rsp[slot + 8] = rs1;
            }
        }
    }
#undef LOAD_STAGE
}

// ============================================================================
// reduce 32 row-sum partials per row -> rowsum.
// ============================================================================
__global__ __launch_bounds__(256)
void rowsum_reduce(const float* __restrict__ rsp, float* __restrict__ rsum)
{
    const int i = blockIdx.x * 256 + threadIdx.x;
    float s = 0.f;
    #pragma unroll
    for (int j = 0; j < 32; j++) s += rsp[(long)j * MSROWS + i];
    rsum[i] = s;
}

// ============================================================================
// batched 1024x1024 transpose fp32 -> fp16: 4 weights in one launch (z=0..3).
// ============================================================================
__global__ __launch_bounds__(256)
void transpose4_kernel(const float* __restrict__ s0, const float* __restrict__ s1,
                       const float* __restrict__ s2, const float* __restrict__ s3,
                       __half* __restrict__ d0, __half* __restrict__ d1,
                       __half* __restrict__ d2, __half* __restrict__ d3)
{
    __shared__ __half tile[32][34];
    const float* src = (blockIdx.z == 0) ? s0 : (blockIdx.z == 1) ? s1
                     : (blockIdx.z == 2) ? s2 : s3;
    __half* dst = (blockIdx.z == 0) ? d0 : (blockIdx.z == 1) ? d1
                : (blockIdx.z == 2) ? d2 : d3;
    const int c0 = blockIdx.x * 32, r0 = blockIdx.y * 32;
    const int tx = threadIdx.x, ty = threadIdx.y;
    #pragma unroll
    for (int i = ty; i < 32; i += 8)
        tile[i][tx] = __float2half_rn(src[(long)(r0 + i) * 1024 + c0 + tx]);
    __syncthreads();
    #pragma unroll
    for (int i = ty; i < 32; i += 8)
        dst[(long)(c0 + i) * 1024 + r0 + tx] = tile[tx][i];
}

// elementwise fp32 -> fp16 (for x)
__global__ __launch_bounds__(256)
void cvt_kernel(const float4* __restrict__ in, __half2* __restrict__ out, long n4)
{
    long i = blockIdx.x * 256L + threadIdx.x;
    const long stride = gridDim.x * 256L;
    for (; i < n4; i += stride) {
        float4 v = in[i];
        out[i * 2]     = __floats2half2_rn(v.x, v.y);
        out[i * 2 + 1] = __floats2half2_rn(v.z, v.w);
    }
}

// ============================================================================
extern "C" void kernel_launch(void* const* d_in, const int* in_sizes, int n_in,
                              void* d_out, int out_size)
{
    (void)in_sizes; (void)n_in; (void)out_size;
    const float* x  = (const float*)d_in[0];
    const float* wq = (const float*)d_in[1];
    const float* bq = (const float*)d_in[2];
    const float* wk = (const float*)d_in[3];
    const float* bk = (const float*)d_in[4];
    const float* wv = (const float*)d_in[5];
    const float* bv = (const float*)d_in[6];
    const float* wo = (const float*)d_in[7];
    const float* bo = (const float*)d_in[8];
    float* out = (float*)d_out;

    __half *xc, *qk, *vt, *ctx, *e, *wqkT, *wvT, *woT;
    float *bqk, *rsp, *rs;
    cudaGetSymbolAddress((void**)&xc,   g_xc);
    cudaGetSymbolAddress((void**)&qk,   g_qk);
    cudaGetSymbolAddress((void**)&vt,   g_vt);
    cudaGetSymbolAddress((void**)&ctx,  g_ctx);
    cudaGetSymbolAddress((void**)&e,    g_e);
    cudaGetSymbolAddress((void**)&wqkT, g_wqkT);
    cudaGetSymbolAddress((void**)&wvT,  g_wvT);
    cudaGetSymbolAddress((void**)&woT,  g_woT);
    cudaGetSymbolAddress((void**)&bqk,  g_bqk);
    cudaGetSymbolAddress((void**)&rsp,  g_rsp);
    cudaGetSymbolAddress((void**)&rs,   g_rs);

    const int Bsz = 8, S = 2048, H = 1024;
    const int MS = Bsz * S;                 // 16384
    const float scale = 0.03125f;           // 1/sqrt(1024)

    // template instantiations: <BIAS, MODE, HALF_OUT, LDA, LDB, LDC, K>
    auto gemm_qkproj = h16_gemm<1, 0, true,  1024, 1024, 2048, 1024>;
    auto gemm_vproj  = h16_gemm<2, 0, true,  1024, 1024, 2048, 1024>;
    auto gemm_energy = h16_gemm<0, 1, true,  2048, 2048, 2048, 1024>;
    auto gemm_ctx    = h16_gemm<0, 2, true,  2048, 2048, 1024, 2048>;
    auto gemm_out    = h16_gemm<1, 0, false, 1024, 1024, 1024, 1024>;

    cudaFuncSetAttribute(gemm_qkproj, cudaFuncAttributeMaxDynamicSharedMemorySize, SMEM_BYTES);
    cudaFuncSetAttribute(gemm_vproj,  cudaFuncAttributeMaxDynamicSharedMemorySize, SMEM_BYTES);
    cudaFuncSetAttribute(gemm_energy, cudaFuncAttributeMaxDynamicSharedMemorySize, SMEM_BYTES);
    cudaFuncSetAttribute(gemm_ctx,    cudaFuncAttributeMaxDynamicSharedMemorySize, SMEM_BYTES);
    cudaFuncSetAttribute(gemm_out,    cudaFuncAttributeMaxDynamicSharedMemorySize, SMEM_BYTES);

    // convert x to fp16
    cvt_kernel<<<1024, 256>>>((const float4*)x, (__half2*)xc, (long)MS * H / 4);

    // all 4 weight transposes (fp32 -> fp16) in one launch
    transpose4_kernel<<<dim3(32, 32, 4), dim3(32, 8)>>>(
        wq, wk, wv, wo, wqkT, wqkT + (long)H * H, wvT, woT);
    cudaMemcpyAsync(bqk,     bq, H * sizeof(float), cudaMemcpyDeviceToDevice);
    cudaMemcpyAsync(bqk + H, bk, H * sizeof(float), cudaMemcpyDeviceToDevice);

    dim3 blk(128);

    // Q+K projection, merged: qk[MS, 2048] = xc @ wqkT^T + bqk
    gemm_qkproj<<<dim3(2 * H / BN, MS / BM, 1), blk, SMEM_BYTES>>>(
        xc, wqkT, bqk, qk, 0, 0, 0, 1.f, nullptr, nullptr, 0);

    // V, produced transposed: vt[b] (H x S) = wvT @ x[b]^T + bv (row bias)
    gemm_vproj<<<dim3(S / BN, H / BM, Bsz), blk, SMEM_BYTES>>>(
        wvT, xc, bv, vt, 0, (long)S * H, (long)H * S, 1.f, nullptr, nullptr, 0);

    // Energy + exp fused: P = exp(scale * Q @ K^T), row-sum partials emitted.
    gemm_energy<<<dim3(S / BN, S / BM, Bsz), blk, SMEM_BYTES>>>(
        qk, qk + H, nullptr, e,
        (long)S * 2 * H, (long)S * 2 * H, (long)S * S, scale,
        nullptr, rsp, (long)S);

    rowsum_reduce<<<MS / 256, 256>>>(rsp, rs);

    // Context: ctx = (P @ V) / rowsum
    gemm_ctx<<<dim3(H / BN, S / BM, Bsz), blk, SMEM_BYTES>>>(
        e, vt, nullptr, ctx,
        (long)S * S, (long)H * S, (long)S * H, 1.f, rs, nullptr, (long)S);

    // Output projection (fp32 output)
    gemm_out<<<dim3(H / BN, MS / BM, 1), blk, SMEM_BYTES>>>(
        ctx, woT, bo, out, 0, 0, 0, 1.f, nullptr, nullptr, 0);
}

// round 15
// speedup vs baseline: 2.8117x; 1.0020x over previous
#include <cuda_runtime.h>
#include <cuda_fp16.h>
#include <cstdint>

// ============================================================================
// SpecAttn via mma.sync fp16 m16n8k16 (fp32 accumulate). R14: same validated
// skeleton (128x128 tile, 128 thr, 2x2 warp grid, 2 CTAs/SM, ST=2) but fp16
// operands: BK=64/iter, ONE LDS.64 per fragment (4tg k-relabel), half the
// HMMA count, half the smem/L2 traffic, half the barriers.
// Numerics: fp16 significand == tf32 significand (11 bits); energies bounded
// (|s|<~2.5) so P=exp(s) in [0.08, 12] — far from fp16 limits. fp32 accum.
// ============================================================================

#define BM 128
#define BN 128
#define BK 64                           // K halves per iteration
#define ST 2
#define ROWFH 80                        // 64 data + 16 pad halves; conflict-free
#define TILE_H (BM * ROWFH)             // 10240 halves = 20480 B
#define STAGE_H (2 * TILE_H)            // A + B per stage
#define SMEM_BYTES (ST * STAGE_H * 2)   // 81920 B -> 2 CTAs/SM

#define MSROWS 16384                    // B*S

// ---------------- scratch (device globals; no allocations) ------------------
__device__ __half g_xc  [8L*2048*1024];
__device__ __half g_qk  [16384L*2048];   // cols 0-1023 = Q, 1024+ = K
__device__ __half g_vt  [8L*1024*2048];  // per batch [H, S]
__device__ __half g_ctx [8L*2048*1024];
__device__ __half g_e   [8L*2048*2048];
__device__ __half g_wqkT[2048L*1024];    // rows 0-1023 wq^T, 1024+ wk^T
__device__ __half g_wvT [1024L*1024];
__device__ __half g_woT [1024L*1024];
__device__ float  g_bqk [2048];
__device__ float  g_rsp [32L*MSROWS];    // per-(bx,nwarp) row-sum partials
__device__ float  g_rs  [MSROWS];        // reduced row sums

// ---------------- helpers ----------------------------------------------------
__device__ __forceinline__ uint32_t smem_u32(const void* p) {
    uint32_t a;
    asm("{ .reg .u64 t; cvta.to.shared.u64 t, %1; cvt.u32.u64 %0, t; }" : "=r"(a) : "l"(p));
    return a;
}
__device__ __forceinline__ void mma_f16(float* c, const uint32_t* a, const uint32_t* b) {
    asm volatile(
        "mma.sync.aligned.m16n8k16.row.col.f32.f16.f16.f32 "
        "{%0,%1,%2,%3},{%4,%5,%6,%7},{%8,%9},{%0,%1,%2,%3};"
        : "+f"(c[0]), "+f"(c[1]), "+f"(c[2]), "+f"(c[3])
        : "r"(a[0]), "r"(a[1]), "r"(a[2]), "r"(a[3]), "r"(b[0]), "r"(b[1]));
}

// ============================================================================
// fp16 GEMM: C[z] = f( alpha * A[z] @ B[z]^T + bias )   (fp32 accumulate)
//   BIAS: 0 none, 1 per-column (fp32), 2 per-row (fp32).
//   MODE: 0 plain, 1 f=exp + row-sum partials, 2 scale rows by 1/rowsum.
//   HALF_OUT: store __half2 (intermediates) or float2 (final output).
//   LDA/LDB/LDC in halves (compile-time).  K mult of 64.
// grid = (N/BN, M/BM, Z), block = 128 (4 warps, 2x2 grid, 64x64 warp tiles).
// k16-group relabel: logical k slots {2tg,2tg+1,2tg+8,2tg+9} <- smem halves
// {4tg..4tg+3} of the group — one LDS.64 per fragment, bijective over tg,
// applied identically to A and B (contraction order within k16 is free).
// ============================================================================
template <int BIAS, int MODE, bool HALF_OUT, int LDA, int LDB, int LDC, int K>
__global__ __launch_bounds__(128, 2)
void h16_gemm(const __half* __restrict__ A, const __half* __restrict__ Bm,
              const float* __restrict__ bias, void* __restrict__ Cv,
              long sA, long sB, long sC, float alpha,
              const float* __restrict__ rsum, float* __restrict__ rsp,
              long rsStride)
{
    extern __shared__ __half smh[];
    const uint32_t sbase = smem_u32(smh);
    const int tid = threadIdx.x;

    A  += (long)blockIdx.z * sA;
    Bm += (long)blockIdx.z * sB;
    const long rowBase = (long)blockIdx.y * BM;
    const long colBase = (long)blockIdx.x * BN;
    const long rsBase  = (long)blockIdx.z * rsStride + rowBase;

    // ---- global->smem mapping: thread covers rows (tid>>3)+16i, seg tid&7 ----
    const int lr = tid >> 3;           // 0..15
    const int ls = tid & 7;            // 16B segment within 128B (64-half) row
    const uint32_t off0 = (uint32_t)(lr * (ROWFH * 2) + ls * 16);   // bytes
    const __half* Ag = A  + (rowBase + lr) * (long)LDA + ls * 8;
    const __half* Bg = Bm + (colBase + lr) * (long)LDB + ls * 8;

    const int NT = K / BK;

#define LOAD_STAGE(sbuf, kt) do {                                              \
    const uint32_t st_ = sbase + (uint32_t)(sbuf) * (STAGE_H * 2);             \
    const uint32_t bt_ = st_ + TILE_H * 2;                                     \
    const int ko_ = (kt) * BK;                                                 \
    _Pragma("unroll")                                                          \
    for (int i_ = 0; i_ < 8; i_++) {                                           \
        asm volatile("cp.async.cg.shared.global [%0],[%1],16;"                 \
            :: "r"(st_ + off0 + (uint32_t)i_ * (16 * ROWFH * 2)),              \
               "l"(Ag + ko_ + 16 * i_ * LDA) : "memory");                      \
        asm volatile("cp.async.cg.shared.global [%0],[%1],16;"                 \
            :: "r"(bt_ + off0 + (uint32_t)i_ * (16 * ROWFH * 2)),              \
               "l"(Bg + ko_ + 16 * i_ * LDB) : "memory");                      \
    }                                                                          \
    asm volatile("cp.async.commit_group;" ::: "memory");                       \
} while (0)

    // prologue
    LOAD_STAGE(0, 0);

    // ---- warp tiling: 2x2 warp grid, 64x64 per warp ----
    const int warp = tid >> 5, lane = tid & 31;
    const int grp = lane >> 2, tg = lane & 3;
    const int mbase = (warp & 1) * 64;
    const int nbase = (warp >> 1) * 64;

    float acc[4][8][4];
    #pragma unroll
    for (int mt = 0; mt < 4; mt++)
        #pragma unroll
        for (int nt = 0; nt < 8; nt++)
            #pragma unroll
            for (int j = 0; j < 4; j++) acc[mt][nt][j] = 0.f;

    for (int t = 0; t < NT; ++t) {
        asm volatile("cp.async.wait_group 0;" ::: "memory");
        __syncthreads();
        if (t + 1 < NT) LOAD_STAGE((t + 1) & 1, t + 1);

        const __half* sAt = smh + (t & 1) * STAGE_H;
        const __half* sBt = sAt + TILE_H;

        #pragma unroll
        for (int g = 0; g < 4; g++) {          // four k16 groups per BK=64
            const int gk = g * 16 + 4 * tg;    // halves offset of thread's 4
            uint32_t a[4][4], b[8][2];
            #pragma unroll
            for (int mt = 0; mt < 4; mt++) {
                const int r = mbase + mt * 16 + grp;
                const uint2 v0 = *(const uint2*)(sAt + r * ROWFH + gk);
                const uint2 v1 = *(const uint2*)(sAt + (r + 8) * ROWFH + gk);
                a[mt][0] = v0.x; a[mt][2] = v0.y;
                a[mt][1] = v1.x; a[mt][3] = v1.y;
            }
            #pragma unroll
            for (int nt = 0; nt < 8; nt++) {
                const uint2 w = *(const uint2*)(sBt + (nbase + nt * 8 + grp) * ROWFH + gk);
                b[nt][0] = w.x; b[nt][1] = w.y;
            }
            #pragma unroll
            for (int mt = 0; mt < 4; mt++)
                #pragma unroll
                for (int nt = 0; nt < 8; nt++)
                    mma_f16(acc[mt][nt], a[mt], b[nt]);
        }
    }

    // ---- epilogue (mt-outer so MODE 1/2 and row-bias work per-row) ----
    float2 bv[8];
    #pragma unroll
    for (int nt = 0; nt < 8; nt++) {
        if (BIAS == 1) bv[nt] = *(const float2*)(bias + colBase + nbase + nt * 8 + tg * 2);
        else           bv[nt] = make_float2(0.f, 0.f);
    }

    __half* Ch = (__half*)Cv + (long)blockIdx.z * sC;
    float*  Cf = (float*)Cv  + (long)blockIdx.z * sC;

    #pragma unroll
    for (int mt = 0; mt < 4; mt++) {
        const int rloc = mbase + mt * 16 + grp;      // local row (and +8)
        const long r0 = rowBase + rloc;
        float rb0 = 0.f, rb1 = 0.f;
        if (BIAS == 2) {
            rb0 = bias[r0];
            rb1 = bias[r0 + 8];
        }
        float inv0 = 1.f, inv1 = 1.f;
        if (MODE == 2) {
            inv0 = 1.f / rsum[rsBase + rloc];
            inv1 = 1.f / rsum[rsBase + rloc + 8];
        }
        float rs0 = 0.f, rs1 = 0.f;
        #pragma unroll
        for (int nt = 0; nt < 8; nt++) {
            const long col = colBase + nbase + nt * 8 + tg * 2;
            float o0 = acc[mt][nt][0] * alpha + bv[nt].x + rb0;
            float o1 = acc[mt][nt][1] * alpha + bv[nt].y + rb0;
            float o2 = acc[mt][nt][2] * alpha + bv[nt].x + rb1;
            float o3 = acc[mt][nt][3] * alpha + bv[nt].y + rb1;
            if (MODE == 1) {
                o0 = __expf(o0); o1 = __expf(o1);
                o2 = __expf(o2); o3 = __expf(o3);
                rs0 += o0 + o1;  rs1 += o2 + o3;
            }
            if (MODE == 2) {
                o0 *= inv0; o1 *= inv0; o2 *= inv1; o3 *= inv1;
            }
            if (HALF_OUT) {
                *(__half2*)(Ch + r0 * (long)LDC + col)       = __floats2half2_rn(o0, o1);
                *(__half2*)(Ch + (r0 + 8) * (long)LDC + col) = __floats2half2_rn(o2, o3);
            } else {
                *(float2*)(Cf + r0 * (long)LDC + col)       = make_float2(o0, o1);
                *(float2*)(Cf + (r0 + 8) * (long)LDC + col) = make_float2(o2, o3);
            }
        }
        if (MODE == 1) {
            rs0 += __shfl_xor_sync(~0u, rs0, 1);
            rs0 += __shfl_xor_sync(~0u, rs0, 2);
            rs1 += __shfl_xor_sync(~0u, rs1, 1);
            rs1 += __shfl_xor_sync(~0u, rs1, 2);
            if (tg == 0) {
                const long slot = ((long)blockIdx.x * 2 + (warp >> 1)) * MSROWS + rsBase + rloc;
                rsp[slot]     = rs0;
                rsp[slot + 8] = rs1;
            }
        }
    }
#undef LOAD_STAGE
}

// ============================================================================
// reduce 32 row-sum partials per row -> rowsum.
// ============================================================================
__global__ __launch_bounds__(256)
void rowsum_reduce(const float* __restrict__ rsp, float* __restrict__ rsum)
{
    const int i = blockIdx.x * 256 + threadIdx.x;
    float s = 0.f;
    #pragma unroll
    for (int j = 0; j < 32; j++) s += rsp[(long)j * MSROWS + i];
    rsum[i] = s;
}

// ============================================================================
// batched 1024x1024 transpose fp32 -> fp16: 4 weights in one launch (z=0..3).
// ============================================================================
__global__ __launch_bounds__(256)
void transpose4_kernel(const float* __restrict__ s0, const float* __restrict__ s1,
                       const float* __restrict__ s2, const float* __restrict__ s3,
                       __half* __restrict__ d0, __half* __restrict__ d1,
                       __half* __restrict__ d2, __half* __restrict__ d3)
{
    __shared__ __half tile[32][34];
    const float* src = (blockIdx.z == 0) ? s0 : (blockIdx.z == 1) ? s1
                     : (blockIdx.z == 2) ? s2 : s3;
    __half* dst = (blockIdx.z == 0) ? d0 : (blockIdx.z == 1) ? d1
                : (blockIdx.z == 2) ? d2 : d3;
    const int c0 = blockIdx.x * 32, r0 = blockIdx.y * 32;
    const int tx = threadIdx.x, ty = threadIdx.y;
    #pragma unroll
    for (int i = ty; i < 32; i += 8)
        tile[i][tx] = __float2half_rn(src[(long)(r0 + i) * 1024 + c0 + tx]);
    __syncthreads();
    #pragma unroll
    for (int i = ty; i < 32; i += 8)
        dst[(long)(c0 + i) * 1024 + r0 + tx] = tile[tx][i];
}

// elementwise fp32 -> fp16 (for x)
__global__ __launch_bounds__(256)
void cvt_kernel(const float4* __restrict__ in, __half2* __restrict__ out, long n4)
{
    long i = blockIdx.x * 256L + threadIdx.x;
    const long stride = gridDim.x * 256L;
    for (; i < n4; i += stride) {
        float4 v = in[i];
        out[i * 2]     = __floats2half2_rn(v.x, v.y);
        out[i * 2 + 1] = __floats2half2_rn(v.z, v.w);
    }
}

// ============================================================================
extern "C" void kernel_launch(void* const* d_in, const int* in_sizes, int n_in,
                              void* d_out, int out_size)
{
    (void)in_sizes; (void)n_in; (void)out_size;
    const float* x  = (const float*)d_in[0];
    const float* wq = (const float*)d_in[1];
    const float* bq = (const float*)d_in[2];
    const float* wk = (const float*)d_in[3];
    const float* bk = (const float*)d_in[4];
    const float* wv = (const float*)d_in[5];
    const float* bv = (const float*)d_in[6];
    const float* wo = (const float*)d_in[7];
    const float* bo = (const float*)d_in[8];
    float* out = (float*)d_out;

    __half *xc, *qk, *vt, *ctx, *e, *wqkT, *wvT, *woT;
    float *bqk, *rsp, *rs;
    cudaGetSymbolAddress((void**)&xc,   g_xc);
    cudaGetSymbolAddress((void**)&qk,   g_qk);
    cudaGetSymbolAddress((void**)&vt,   g_vt);
    cudaGetSymbolAddress((void**)&ctx,  g_ctx);
    cudaGetSymbolAddress((void**)&e,    g_e);
    cudaGetSymbolAddress((void**)&wqkT, g_wqkT);
    cudaGetSymbolAddress((void**)&wvT,  g_wvT);
    cudaGetSymbolAddress((void**)&woT,  g_woT);
    cudaGetSymbolAddress((void**)&bqk,  g_bqk);
    cudaGetSymbolAddress((void**)&rsp,  g_rsp);
    cudaGetSymbolAddress((void**)&rs,   g_rs);

    const int Bsz = 8, S = 2048, H = 1024;
    const int MS = Bsz * S;                 // 16384
    const float scale = 0.03125f;           // 1/sqrt(1024)

    // template instantiations: <BIAS, MODE, HALF_OUT, LDA, LDB, LDC, K>
    auto gemm_qkproj = h16_gemm<1, 0, true,  1024, 1024, 2048, 1024>;
    auto gemm_vproj  = h16_gemm<2, 0, true,  1024, 1024, 2048, 1024>;
    auto gemm_energy = h16_gemm<0, 1, true,  2048, 2048, 2048, 1024>;
    auto gemm_ctx    = h16_gemm<0, 2, true,  2048, 2048, 1024, 2048>;
    auto gemm_out    = h16_gemm<1, 0, false, 1024, 1024, 1024, 1024>;

    cudaFuncSetAttribute(gemm_qkproj, cudaFuncAttributeMaxDynamicSharedMemorySize, SMEM_BYTES);
    cudaFuncSetAttribute(gemm_vproj,  cudaFuncAttributeMaxDynamicSharedMemorySize, SMEM_BYTES);
    cudaFuncSetAttribute(gemm_energy, cudaFuncAttributeMaxDynamicSharedMemorySize, SMEM_BYTES);
    cudaFuncSetAttribute(gemm_ctx,    cudaFuncAttributeMaxDynamicSharedMemorySize, SMEM_BYTES);
    cudaFuncSetAttribute(gemm_out,    cudaFuncAttributeMaxDynamicSharedMemorySize, SMEM_BYTES);

    // convert x to fp16
    cvt_kernel<<<1024, 256>>>((const float4*)x, (__half2*)xc, (long)MS * H / 4);

    // all 4 weight transposes (fp32 -> fp16) in one launch
    transpose4_kernel<<<dim3(32, 32, 4), dim3(32, 8)>>>(
        wq, wk, wv, wo, wqkT, wqkT + (long)H * H, wvT, woT);
    cudaMemcpyAsync(bqk,     bq, H * sizeof(float), cudaMemcpyDeviceToDevice);
    cudaMemcpyAsync(bqk + H, bk, H * sizeof(float), cudaMemcpyDeviceToDevice);

    dim3 blk(128);

    // Q+K projection, merged: qk[MS, 2048] = xc @ wqkT^T + bqk
    gemm_qkproj<<<dim3(2 * H / BN, MS / BM, 1), blk, SMEM_BYTES>>>(
        xc, wqkT, bqk, qk, 0, 0, 0, 1.f, nullptr, nullptr, 0);

    // V, produced transposed: vt[b] (H x S) = wvT @ x[b]^T + bv (row bias)
    gemm_vproj<<<dim3(S / BN, H / BM, Bsz), blk, SMEM_BYTES>>>(
        wvT, xc, bv, vt, 0, (long)S * H, (long)H * S, 1.f, nullptr, nullptr, 0);

    // Energy + exp fused: P = exp(scale * Q @ K^T), row-sum partials emitted.
    gemm_energy<<<dim3(S / BN, S / BM, Bsz), blk, SMEM_BYTES>>>(
        qk, qk + H, nullptr, e,
        (long)S * 2 * H, (long)S * 2 * H, (long)S * S, scale,
        nullptr, rsp, (long)S);

    rowsum_reduce<<<MS / 256, 256>>>(rsp, rs);

    // Context: ctx = (P @ V) / rowsum
    gemm_ctx<<<dim3(H / BN, S / BM, Bsz), blk, SMEM_BYTES>>>(
        e, vt, nullptr, ctx,
        (long)S * S, (long)H * S, (long)S * H, 1.f, rs, nullptr, (long)S);

    // Output projection (fp32 output)
    gemm_out<<<dim3(H / BN, MS / BM, 1), blk, SMEM_BYTES>>>(
        ctx, woT, bo, out, 0, 0, 0, 1.f, nullptr, nullptr, 0);
}